// round 1
// baseline (speedup 1.0000x reference)
#include <cuda_runtime.h>
#include <math.h>

#define KTAGS 64
#define DDIM  128
#define VWORDS 50000
#define NV   (VWORDS + 2)
#define BATCHN 2048
#define TLEN 256
#define BOS_TAG 63
#define EOS_TAG 62
#define TINYV 1e-45f

#define SPB  16      // sentences per block in scan
#define ASTR 68      // padded stride (64 + 4) for shared alpha / Th tiles

// Scratch (static device globals: allowed; no dynamic allocation anywhere)
__device__ float g_A[KTAGS * KTAGS];                 // A' = exp(WA)/64, col BOS zeroed
__device__ float g_Bt[(size_t)NV * KTAGS];           // emission table, word-major [w][k]

// ---------------------------------------------------------------------------
// Kernel 1: transition matrix prep.  A'[i][j] = exp(WA[i][j]) / 64, A'[:,BOS]=0
// ---------------------------------------------------------------------------
__global__ void prep_A_kernel(const float* __restrict__ WA) {
    int idx = blockIdx.x * blockDim.x + threadIdx.x;
    if (idx < KTAGS * KTAGS) {
        int j = idx & (KTAGS - 1);
        float v = (j == BOS_TAG) ? 0.0f : expf(WA[idx]) * (1.0f / 64.0f);
        g_A[idx] = v;
    }
}

// ---------------------------------------------------------------------------
// Kernel 2: emission table.  g_Bt[w][k] = exp(dot(ThetaB[k,:], E[w,:]))
// with columns k==EOS_TAG / k==BOS_TAG forced to TINY (as reference updateAB).
// Block = 256 threads handles 64 words x 64 tags, K-dim chunked 2x64 in smem.
// ---------------------------------------------------------------------------
__global__ __launch_bounds__(256) void emit_table_kernel(
        const float* __restrict__ ThetaB, const float* __restrict__ E) {
    __shared__ float sE[64 * 65];     // [w_local][d_local], pad 65 vs bank conflicts
    __shared__ float sTh[64 * ASTR];  // [d_local][k], padded, float4-aligned reads

    int tid = threadIdx.x;
    int wq  = tid & 15;    // word quad (4 words each)
    int kq  = tid >> 4;    // tag quad  (4 tags each)
    int w0  = blockIdx.x * 64;

    float acc[4][4];
#pragma unroll
    for (int a = 0; a < 4; a++)
#pragma unroll
        for (int b = 0; b < 4; b++) acc[a][b] = 0.0f;

    for (int dc = 0; dc < 2; dc++) {
        // stage ThetaB chunk transposed: sTh[dl][k]
        for (int idx = tid; idx < 64 * 64; idx += 256) {
            int k = idx >> 6, dl = idx & 63;
            sTh[dl * ASTR + k] = ThetaB[k * DDIM + dc * 64 + dl];
        }
        // stage E tile: sE[w][dl]
        for (int idx = tid; idx < 64 * 64; idx += 256) {
            int w = idx >> 6, dl = idx & 63;
            int wg = w0 + w;
            sE[w * 65 + dl] = (wg < NV) ? E[(size_t)wg * DDIM + dc * 64 + dl] : 0.0f;
        }
        __syncthreads();

#pragma unroll 8
        for (int dl = 0; dl < 64; dl++) {
            float4 th = *(const float4*)&sTh[dl * ASTR + kq * 4];
#pragma unroll
            for (int ww = 0; ww < 4; ww++) {
                float e = sE[(wq * 4 + ww) * 65 + dl];
                acc[ww][0] += e * th.x;
                acc[ww][1] += e * th.y;
                acc[ww][2] += e * th.z;
                acc[ww][3] += e * th.w;
            }
        }
        __syncthreads();
    }

#pragma unroll
    for (int ww = 0; ww < 4; ww++) {
        int w = w0 + wq * 4 + ww;
        if (w < NV) {
            float4 r;
            r.x = expf(acc[ww][0]);
            r.y = expf(acc[ww][1]);
            r.z = expf(acc[ww][2]);
            r.w = expf(acc[ww][3]);
            if (kq == 15) { r.z = TINYV; r.w = TINYV; }  // tags 62 (EOS), 63 (BOS)
            *(float4*)&g_Bt[(size_t)w * KTAGS + kq * 4] = r;
        }
    }
}

// ---------------------------------------------------------------------------
// Kernel 3: the forward scan.
// 128 CTAs x 16 sentences. 128 threads: s = tid>>3 (16 sentences),
// jq = tid&7 (8 output tags per thread). A' in smem (broadcast within warp:
// 4 sentences share each A read). Fixed 1/64 scaling folded into A'.
// logZ = log(alpha_final @ A'[:,EOS]) + 255*6*ln2.
// ---------------------------------------------------------------------------
__global__ __launch_bounds__(128, 1) void crf_scan_kernel(
        const int* __restrict__ words, float* __restrict__ out) {
    __shared__ float sA[KTAGS * KTAGS];          // 16 KB
    __shared__ float sAl[2][SPB * ASTR];         // double-buffered alpha, 8.5 KB
    __shared__ int   sW[SPB * TLEN];             // words for this block, 16 KB

    int tid = threadIdx.x;
    int s   = tid >> 3;        // 0..15 local sentence
    int jq  = tid & 7;         // 0..7  tag-octet
    int s0  = blockIdx.x * SPB;

    for (int idx = tid; idx < KTAGS * KTAGS; idx += 128) sA[idx] = g_A[idx];
    for (int idx = tid; idx < SPB * TLEN; idx += 128) {
        int ss = idx >> 8, t = idx & (TLEN - 1);
        sW[idx] = words[(size_t)(s0 + ss) * TLEN + t];
    }
    for (int idx = tid; idx < SPB * ASTR; idx += 128) {
        sAl[0][idx] = 0.0f;
        sAl[1][idx] = 0.0f;
    }
    __syncthreads();
    if (tid < SPB) sAl[0][tid * ASTR + BOS_TAG] = 1.0f;  // alpha0 one-hot at BOS
    __syncthreads();

    int p = 0;
    const float* Ab = sA + (jq << 3);  // this thread's 8 A'-columns base

    for (int t = 1; t <= TLEN - 2; ++t) {
        // prefetch emissions for this step (L2-resident table)
        int w = sW[s * TLEN + t];
        const float4* br = (const float4*)(g_Bt + ((size_t)w << 6) + (jq << 3));
        float4 e0 = __ldg(br);
        float4 e1 = __ldg(br + 1);

        float4 acc0 = make_float4(0.f, 0.f, 0.f, 0.f);
        float4 acc1 = make_float4(0.f, 0.f, 0.f, 0.f);
        const float* al = &sAl[p][s * ASTR];

#pragma unroll
        for (int i = 0; i < KTAGS; i += 4) {
            float4 av = *(const float4*)(al + i);
#pragma unroll
            for (int ii = 0; ii < 4; ii++) {
                float a = (ii == 0) ? av.x : (ii == 1) ? av.y : (ii == 2) ? av.z : av.w;
                float4 x = *(const float4*)(Ab + ((i + ii) << 6));
                float4 y = *(const float4*)(Ab + ((i + ii) << 6) + 4);
                acc0.x += a * x.x; acc0.y += a * x.y; acc0.z += a * x.z; acc0.w += a * x.w;
                acc1.x += a * y.x; acc1.y += a * y.y; acc1.z += a * y.z; acc1.w += a * y.w;
            }
        }

        float* dst = &sAl[p ^ 1][s * ASTR + (jq << 3)];
        float4 n0 = make_float4(acc0.x * e0.x, acc0.y * e0.y, acc0.z * e0.z, acc0.w * e0.w);
        float4 n1 = make_float4(acc1.x * e1.x, acc1.y * e1.y, acc1.z * e1.z, acc1.w * e1.w);
        *(float4*)dst       = n0;
        *(float4*)(dst + 4) = n1;
        __syncthreads();
        p ^= 1;
    }

    // final transition into EOS tag: z = alpha @ A'[:,EOS]
    {
        const float* al = &sAl[p][s * ASTR];
        float z = 0.0f;
#pragma unroll
        for (int c = 0; c < 8; c++) {
            int i = (jq << 3) + c;
            z += al[i] * sA[i * KTAGS + EOS_TAG];
        }
#pragma unroll
        for (int off = 4; off; off >>= 1)
            z += __shfl_xor_sync(0xffffffffu, z, off);
        if (jq == 0) {
            // + 255 steps * log(64) = 1530 * ln2 (fixed-scaling compensation)
            out[s0 + s] = logf(z) + 1060.5151862567153f;
        }
    }
}

// ---------------------------------------------------------------------------
extern "C" void kernel_launch(void* const* d_in, const int* in_sizes, int n_in,
                              void* d_out, int out_size) {
    // Robustly match inputs by element count (order per metadata: words, ThetaB, WA, E)
    const int*   words  = nullptr;
    const float* ThetaB = nullptr;
    const float* WA     = nullptr;
    const float* E      = nullptr;
    for (int i = 0; i < n_in; i++) {
        switch (in_sizes[i]) {
            case BATCHN * TLEN:   words  = (const int*)d_in[i];   break;  // 524288
            case KTAGS * DDIM:    ThetaB = (const float*)d_in[i]; break;  // 8192
            case KTAGS * KTAGS:   WA     = (const float*)d_in[i]; break;  // 4096
            case NV * DDIM:       E      = (const float*)d_in[i]; break;  // 6400256
        }
    }
    float* out = (float*)d_out;

    prep_A_kernel<<<16, 256>>>(WA);
    emit_table_kernel<<<(NV + 63) / 64, 256>>>(ThetaB, E);
    crf_scan_kernel<<<BATCHN / SPB, 128>>>(words, out);
}